// round 5
// baseline (speedup 1.0000x reference)
#include <cuda_runtime.h>

// out[i] = in[i,1] + w*(in[i,0]-in[i,1])
// N = 16777216. Pure streaming, 12 B/elem.
// Best shape (R3, 26.3us kernel, DRAM 78.6%): 4 outputs/thread, two LDG.128
// default-cached loads, __stcs evict-first store.
// Delta vs R3: scalar weight moved to __constant__ (const-cache read instead of
// a per-thread L1tex LDG broadcast) via async D2D copy-to-symbol (capturable).

__constant__ float c_w;

__global__ __launch_bounds__(256)
void skip_kernel(const float4* __restrict__ in,
                 float4* __restrict__ out)
{
    const unsigned i = blockIdx.x * blockDim.x + threadIdx.x;
    const float w = c_w;

    float4 a = __ldg(&in[2u * i]);
    float4 b = __ldg(&in[2u * i + 1u]);

    float4 o;
    o.x = fmaf(w, a.x - a.y, a.y);
    o.y = fmaf(w, a.z - a.w, a.w);
    o.z = fmaf(w, b.x - b.y, b.y);
    o.w = fmaf(w, b.z - b.w, b.w);

    __stcs(&out[i], o);
}

extern "C" void kernel_launch(void* const* d_in, const int* in_sizes, int n_in,
                              void* d_out, int out_size)
{
    const float* input  = (const float*)d_in[0];   // [N,2]
    const float* weight = (const float*)d_in[1];   // [1,1]
    float*       out    = (float*)d_out;           // [N,1]

    // Async device-to-device copy of the scalar into constant memory.
    // Graph-capturable (memcpy node), no allocation.
    cudaMemcpyToSymbolAsync(c_w, weight, sizeof(float), 0,
                            cudaMemcpyDeviceToDevice);

    const int n = in_sizes[0] / 2;     // 16777216 outputs
    const int n4 = n / 4;              // 4 outputs per thread, exact
    const int threads = 256;
    const int blocks = n4 / threads;   // 16384

    skip_kernel<<<blocks, threads>>>((const float4*)input, (float4*)out);
}

// round 6
// speedup vs baseline: 1.0136x; 1.0136x over previous
#include <cuda_runtime.h>

// out[k] = in[k,1] + w*(in[k,0]-in[k,1]).  N = 16777216, pure streaming.
// Dense warp-cooperative layout: lane L of warp W loads in4[64W+L] and
// in4[64W+32+L] — two dense 512B warp segments (100% sector utilization,
// 4 L1tex wavefronts per LDG vs 8 for the per-thread-adjacent pattern).
// Each float4 input = 2 (x,y) pairs = 2 outputs -> dense float2 store.
// Cache policy (proven R3): default-cached loads, evict-first stores.

__global__ __launch_bounds__(256)
void skip_kernel(const float4* __restrict__ in,
                 const float* __restrict__ w_ptr,
                 float2* __restrict__ out)
{
    const unsigned tid  = blockIdx.x * blockDim.x + threadIdx.x;
    const unsigned warp = tid >> 5;
    const unsigned lane = tid & 31u;
    const unsigned base = warp * 64u + lane;   // float4 index

    const float w = __ldg(w_ptr);

    float4 a = __ldg(&in[base]);
    float4 b = __ldg(&in[base + 32u]);

    float2 oa, ob;
    oa.x = fmaf(w, a.x - a.y, a.y);
    oa.y = fmaf(w, a.z - a.w, a.w);
    ob.x = fmaf(w, b.x - b.y, b.y);
    ob.y = fmaf(w, b.z - b.w, b.w);

    __stcs(&out[base], oa);
    __stcs(&out[base + 32u], ob);
}

extern "C" void kernel_launch(void* const* d_in, const int* in_sizes, int n_in,
                              void* d_out, int out_size)
{
    const float* input  = (const float*)d_in[0];   // [N,2]
    const float* weight = (const float*)d_in[1];   // [1,1]
    float*       out    = (float*)d_out;           // [N,1]

    const int n = in_sizes[0] / 2;     // 16777216 outputs
    const int n_thr = n / 4;           // 4 outputs per thread, exact
    const int threads = 256;
    const int blocks = n_thr / threads; // 16384

    skip_kernel<<<blocks, threads>>>((const float4*)input, weight, (float2*)out);
}